// round 1
// baseline (speedup 1.0000x reference)
#include <cuda_runtime.h>

#define NN 8192

// Scratch (device globals — no allocation allowed in kernel_launch)
__device__ float g_s[NN];
__device__ float g_wmax[NN];
__device__ float g_wmin[NN];

__global__ void precompute_kernel(const float* __restrict__ x,
                                  const float* __restrict__ Wphi) {
    int j = blockIdx.x * blockDim.x + threadIdx.x;
    if (j < NN) {
        g_s[j] = x[j * 3 + 0] + x[j * 3 + 1] + x[j * 3 + 2];
        float w0 = Wphi[j];
        float w1 = Wphi[NN + j];
        float w2 = Wphi[2 * NN + j];
        g_wmax[j] = fmaxf(w0, fmaxf(w1, w2));
        g_wmin[j] = fminf(w0, fminf(w1, w2));
    }
}

__global__ __launch_bounds__(256, 8)
void rowmax_kernel(const int* __restrict__ adj, float* __restrict__ out) {
    const int i = blockIdx.x;
    const float si = g_s[i];

    const int4*   arow = reinterpret_cast<const int4*>(adj + (size_t)i * NN);
    const float4* s4   = reinterpret_cast<const float4*>(g_s);
    const float4* wx4  = reinterpret_cast<const float4*>(g_wmax);
    const float4* wn4  = reinterpret_cast<const float4*>(g_wmin);

    float m = 0.0f;  // reference max always includes T[i,i] = 0

    // NN/4 = 2048 int4 chunks, 256 threads -> 8 iterations
    #pragma unroll
    for (int it = 0; it < (NN / 4) / 256; it++) {
        const int jb = it * 256 + threadIdx.x;
        int4   a  = arow[jb];
        float4 sv = s4[jb];
        float4 wx = wx4[jb];
        float4 wn = wn4[jb];

        float d0 = si - sv.x;
        float d1 = si - sv.y;
        float d2 = si - sv.z;
        float d3 = si - sv.w;

        if (a.x) m = fmaxf(m, fmaxf(d0 * wx.x, d0 * wn.x));
        if (a.y) m = fmaxf(m, fmaxf(d1 * wx.y, d1 * wn.y));
        if (a.z) m = fmaxf(m, fmaxf(d2 * wx.z, d2 * wn.z));
        if (a.w) m = fmaxf(m, fmaxf(d3 * wx.w, d3 * wn.w));
    }

    // Block max-reduce: warp shuffle, then cross-warp via smem
    #pragma unroll
    for (int off = 16; off; off >>= 1)
        m = fmaxf(m, __shfl_xor_sync(0xffffffffu, m, off));

    __shared__ float smax[8];
    if ((threadIdx.x & 31) == 0) smax[threadIdx.x >> 5] = m;
    __syncthreads();

    if (threadIdx.x < 8) {
        m = smax[threadIdx.x];
        #pragma unroll
        for (int off = 4; off; off >>= 1)
            m = fmaxf(m, __shfl_xor_sync(0xffu, m, off));
        if (threadIdx.x == 0) {
            out[i * 3 + 0] = m;
            out[i * 3 + 1] = m;
            out[i * 3 + 2] = m;
        }
    }
}

extern "C" void kernel_launch(void* const* d_in, const int* in_sizes, int n_in,
                              void* d_out, int out_size) {
    const float* x    = (const float*)d_in[0];
    const int*   adj  = (const int*)d_in[1];
    const float* Wphi = (const float*)d_in[2];
    // d_in[3] (W_theta) is unused in the forward pass.
    float* out = (float*)d_out;

    precompute_kernel<<<(NN + 255) / 256, 256>>>(x, Wphi);
    rowmax_kernel<<<NN, 256>>>(adj, out);
}

// round 2
// speedup vs baseline: 1.0446x; 1.0446x over previous
#include <cuda_runtime.h>

#define NN 8192
#define RPB 8           // rows per CTA
#define TPB 256

// Scratch (device globals — no allocation allowed in kernel_launch)
__device__ float g_s[NN];
__device__ float g_wmax[NN];
__device__ float g_wmin[NN];

__global__ void precompute_kernel(const float* __restrict__ x,
                                  const float* __restrict__ Wphi) {
    int j = blockIdx.x * blockDim.x + threadIdx.x;
    if (j < NN) {
        g_s[j] = x[j * 3 + 0] + x[j * 3 + 1] + x[j * 3 + 2];
        float w0 = Wphi[j];
        float w1 = Wphi[NN + j];
        float w2 = Wphi[2 * NN + j];
        g_wmax[j] = fmaxf(w0, fmaxf(w1, w2));
        g_wmin[j] = fminf(w0, fminf(w1, w2));
    }
}

__global__ __launch_bounds__(TPB, 4)
void rowmax_kernel(const int* __restrict__ adj, float* __restrict__ out) {
    const int row0 = blockIdx.x * RPB;

    // Per-row coordinate sums for the RPB rows this CTA owns
    float si[RPB];
    #pragma unroll
    for (int r = 0; r < RPB; r++) si[r] = g_s[row0 + r];

    const float4* s4  = reinterpret_cast<const float4*>(g_s);
    const float4* wx4 = reinterpret_cast<const float4*>(g_wmax);
    const float4* wn4 = reinterpret_cast<const float4*>(g_wmin);

    float m[RPB];
    #pragma unroll
    for (int r = 0; r < RPB; r++) m[r] = 0.0f;   // ref max always includes T[i,i]=0

    // NN/4 = 2048 int4 chunks; TPB threads -> 8 iterations
    #pragma unroll
    for (int it = 0; it < (NN / 4) / TPB; it++) {
        const int jb = it * TPB + threadIdx.x;

        // One set of cached float streams for all RPB rows
        float4 sv = s4[jb];
        float4 wx = wx4[jb];
        float4 wn = wn4[jb];

        // Front-batch the RPB adjacency loads for MLP
        int4 a[RPB];
        #pragma unroll
        for (int r = 0; r < RPB; r++)
            a[r] = reinterpret_cast<const int4*>(adj + (size_t)(row0 + r) * NN)[jb];

        #pragma unroll
        for (int r = 0; r < RPB; r++) {
            float d0 = si[r] - sv.x;
            float d1 = si[r] - sv.y;
            float d2 = si[r] - sv.z;
            float d3 = si[r] - sv.w;
            if (a[r].x) m[r] = fmaxf(m[r], fmaxf(d0 * wx.x, d0 * wn.x));
            if (a[r].y) m[r] = fmaxf(m[r], fmaxf(d1 * wx.y, d1 * wn.y));
            if (a[r].z) m[r] = fmaxf(m[r], fmaxf(d2 * wx.z, d2 * wn.z));
            if (a[r].w) m[r] = fmaxf(m[r], fmaxf(d3 * wx.w, d3 * wn.w));
        }
    }

    // Intra-warp reduce each row's max
    #pragma unroll
    for (int r = 0; r < RPB; r++) {
        #pragma unroll
        for (int off = 16; off; off >>= 1)
            m[r] = fmaxf(m[r], __shfl_xor_sync(0xffffffffu, m[r], off));
    }

    // Cross-warp: 8 warps x RPB rows
    __shared__ float smax[TPB / 32][RPB];
    const int warp = threadIdx.x >> 5;
    if ((threadIdx.x & 31) == 0) {
        #pragma unroll
        for (int r = 0; r < RPB; r++) smax[warp][r] = m[r];
    }
    __syncthreads();

    // 64 threads: thread = r*8 + w reduces row r across 8 warps
    if (threadIdx.x < (TPB / 32) * RPB) {
        const int r = threadIdx.x >> 3;   // row within CTA
        const int w = threadIdx.x & 7;    // warp slot
        float v = smax[w][r];
        #pragma unroll
        for (int off = 4; off; off >>= 1)
            v = fmaxf(v, __shfl_xor_sync(0xffffffffu, v, off));
        if (w == 0) {
            const int i = row0 + r;
            out[i * 3 + 0] = v;
            out[i * 3 + 1] = v;
            out[i * 3 + 2] = v;
        }
    }
}

extern "C" void kernel_launch(void* const* d_in, const int* in_sizes, int n_in,
                              void* d_out, int out_size) {
    const float* x    = (const float*)d_in[0];
    const int*   adj  = (const int*)d_in[1];
    const float* Wphi = (const float*)d_in[2];
    // d_in[3] (W_theta) is unused in the forward pass.
    float* out = (float*)d_out;

    precompute_kernel<<<(NN + 255) / 256, 256>>>(x, Wphi);
    rowmax_kernel<<<NN / RPB, TPB>>>(adj, out);
}